// round 8
// baseline (speedup 1.0000x reference)
#include <cuda_runtime.h>

#define D_DIM 1024
#define L_DIM 24
#define TPB   256
#define CPT   4           // columns per thread: 1024 / 256
#define EPSV  1e-8f
#define FULL  0xffffffffu

typedef unsigned long long ull;

// ---- Blackwell packed fp32x2 ops (PTX ISA 8.6+, sm_100+) ----
__device__ __forceinline__ ull pack2(float lo, float hi) {
    ull r; asm("mov.b64 %0, {%1, %2};" : "=l"(r) : "f"(lo), "f"(hi)); return r;
}
__device__ __forceinline__ void unpack2(ull v, float& lo, float& hi) {
    asm("mov.b64 {%0, %1}, %2;" : "=f"(lo), "=f"(hi) : "l"(v));
}
__device__ __forceinline__ ull mul2(ull a, ull b) {
    ull d; asm("mul.rn.f32x2 %0, %1, %2;" : "=l"(d) : "l"(a), "l"(b)); return d;
}
__device__ __forceinline__ ull ffma2(ull a, ull b, ull c) {
    ull d; asm("fma.rn.f32x2 %0, %1, %2, %3;" : "=l"(d) : "l"(a), "l"(b), "l"(c)); return d;
}

__global__ __launch_bounds__(TPB, 1)
void leech_fused_kernel(const float* __restrict__ data,
                        const float* __restrict__ W_enc,
                        const float* __restrict__ b_enc,
                        const float* __restrict__ W_dec,
                        const float* __restrict__ b_dec,
                        const float* __restrict__ ecs_p,
                        const float* __restrict__ ep_p,
                        float* __restrict__ out,
                        int n_rows)
{
    // double-buffered reduction scratch: [parity][warp*32 + slot]
    // slots 0..23 = proj partials, 24 = ss partial, 25 = oss partial
    __shared__ float sRed[2][8 * 32];

    const int t    = threadIdx.x;
    const int wid  = t >> 5;
    const int lane = t & 31;
    const int c0   = t * CPT;

    // ---- prologue: packed weight slices in registers ----
    // we2[i][k] = (W_enc[2i][c0+k], W_enc[2i+1][c0+k])
    ull we2[L_DIM / 2][4];
    #pragma unroll
    for (int i = 0; i < L_DIM / 2; ++i) {
        float4 a = *reinterpret_cast<const float4*>(&W_enc[(2 * i)     * D_DIM + c0]);
        float4 b = *reinterpret_cast<const float4*>(&W_enc[(2 * i + 1) * D_DIM + c0]);
        we2[i][0] = pack2(a.x, b.x); we2[i][1] = pack2(a.y, b.y);
        we2[i][2] = pack2(a.z, b.z); we2[i][3] = pack2(a.w, b.w);
    }
    // wd2[j][i] = (W_dec[(c0+j)][2i], W_dec[(c0+j)][2i+1])
    ull wd2[CPT][L_DIM / 2];
    #pragma unroll
    for (int j = 0; j < CPT; ++j) {
        #pragma unroll
        for (int i = 0; i < L_DIM / 2; ++i) {
            float2 v = *reinterpret_cast<const float2*>(&W_dec[(c0 + j) * L_DIM + 2 * i]);
            wd2[j][i] = pack2(v.x, v.y);
        }
    }
    const float4 bd  = *reinterpret_cast<const float4*>(&b_dec[c0]);
    const float  ecs = ecs_p[0];
    const float  ep  = ep_p[0];
    const float  benc = (lane < L_DIM) ? b_enc[lane] : 0.0f;

    // split-butterfly final lane -> value-id map (lanes with (lane&3)==3 hold dups)
    const bool dup = ((lane & 3) == 3);
    const int  vid = 12 * ((lane >> 4) & 1) + 6 * ((lane >> 3) & 1)
                   + 3 * ((lane >> 2) & 1) + ((lane & 2) ? 2 : (lane & 1));

    int row = blockIdx.x;
    const int stride = gridDim.x;

    float4 dv = make_float4(0.f, 0.f, 0.f, 0.f);
    if (row < n_rows)
        dv = *reinterpret_cast<const float4*>(&data[(size_t)row * D_DIM + c0]);

    int   p = 0;                 // parity buffer index
    bool  havePrev = false;
    float pr0 = 0.f, pr1 = 0.f, pr2 = 0.f, pr3 = 0.f, pin_e2 = 0.f;
    size_t prow_off = 0;

    for (; row < n_rows; row += stride) {
        // ---- encode: packed FFMA2, weights in registers ----
        const ull dx = pack2(dv.x, dv.x), dy = pack2(dv.y, dv.y);
        const ull dz = pack2(dv.z, dv.z), dw = pack2(dv.w, dv.w);

        ull a2[L_DIM / 2];
        #pragma unroll
        for (int i = 0; i < L_DIM / 2; ++i) {
            ull a = mul2(dx, we2[i][0]);
            a = ffma2(dy, we2[i][1], a);
            a = ffma2(dz, we2[i][2], a);
            a = ffma2(dw, we2[i][3], a);
            a2[i] = a;
        }
        // packed sum-of-squares for in_e
        float ss;
        {
            const ull p01 = pack2(dv.x, dv.y), p23 = pack2(dv.z, dv.w);
            ull sp = mul2(p01, p01);
            sp = ffma2(p23, p23, sp);
            float slo, shi; unpack2(sp, slo, shi);
            ss = slo + shi;
        }

        // prefetch next row (dv dead after encode)
        const int nrow = row + stride;
        float4 dnext = make_float4(0.f, 0.f, 0.f, 0.f);
        if (nrow < n_rows)
            dnext = *reinterpret_cast<const float4*>(&data[(size_t)nrow * D_DIM + c0]);

        // unpack accumulators (register-pair aliasing, near-free)
        float acc[L_DIM];
        #pragma unroll
        for (int i = 0; i < L_DIM / 2; ++i)
            unpack2(a2[i], acc[2 * i], acc[2 * i + 1]);

        // ---- value-split butterfly (same xor tree as naive reduction) ----
        float w12[12];
        #pragma unroll
        for (int i = 0; i < 12; ++i) {
            float don = (lane & 16) ? acc[i] : acc[i + 12];
            float rec = __shfl_xor_sync(FULL, don, 16);
            w12[i] = ((lane & 16) ? acc[i + 12] : acc[i]) + rec;
        }
        float w6[6];
        #pragma unroll
        for (int i = 0; i < 6; ++i) {
            float don = (lane & 8) ? w12[i] : w12[i + 6];
            float rec = __shfl_xor_sync(FULL, don, 8);
            w6[i] = ((lane & 8) ? w12[i + 6] : w12[i]) + rec;
        }
        float w3[3];
        #pragma unroll
        for (int i = 0; i < 3; ++i) {
            float don = (lane & 4) ? w6[i] : w6[i + 3];
            float rec = __shfl_xor_sync(FULL, don, 4);
            w3[i] = ((lane & 4) ? w6[i + 3] : w6[i]) + rec;
        }
        float don4 = (lane & 2) ? w3[0] : w3[2];
        float rec4 = __shfl_xor_sync(FULL, don4, 2);
        float n0 = ((lane & 2) ? w3[2] : w3[0]) + rec4;
        float n1 = w3[1] + __shfl_xor_sync(FULL, w3[1], 2);
        float don5 = (lane & 1) ? n0 : n1;
        float rec5 = __shfl_xor_sync(FULL, don5, 1);
        float fin = ((lane & 1) ? n1 : n0) + rec5;

        #pragma unroll
        for (int off = 16; off > 0; off >>= 1)
            ss += __shfl_xor_sync(FULL, ss, off);

        if (!dup)      sRed[p][wid * 32 + vid] = fin;
        if (lane == 3) sRed[p][wid * 32 + 24]  = ss;
        __syncthreads();                              // the ONLY barrier per row

        // ---- finalize previous row (overlaps this row's lattice math) ----
        if (havePrev) {
            float oe2 = 0.0f;
            #pragma unroll
            for (int w = 0; w < TPB / 32; ++w)
                oe2 += sRed[1 - p][w * 32 + 25];
            const float s2 = pin_e2 / (sqrtf(oe2) + EPSV) * ep;
            float4 o;
            o.x = pr0 * s2; o.y = pr1 * s2; o.z = pr2 * s2; o.w = pr3 * s2;
            *reinterpret_cast<float4*>(&out[prow_off]) = o;
        }

        // ---- lattice math: every warp computes it redundantly (bitwise identical) ----
        float s = 0.0f;
        if (lane <= L_DIM) {
            #pragma unroll
            for (int w = 0; w < TPB / 32; ++w)
                s += sRed[p][w * 32 + lane];
        }
        const float sumsq = __shfl_sync(FULL, s, L_DIM);
        const float in_e  = sqrtf(sumsq);

        float lp = 0.0f;
        if (lane < L_DIM)
            lp = rintf((s + benc) / ecs) * ecs;       // exact div + half-even round
        float q = lp * lp;                            // lanes >= 24 contribute 0
        #pragma unroll
        for (int off = 16; off > 0; off >>= 1)
            q += __shfl_xor_sync(FULL, q, off);
        const float out_e = sqrtf(q);

        const float s1    = in_e / (out_e + EPSV) * ep;
        const float lat   = lp * s1;
        const float cor   = (fabsf(lat) > ecs) ? lat : 0.0f;
        const float in_e2 = fabsf(s1) * out_e;        // ||lattice||

        // ---- decode: packed FFMA2 over l-pairs, cor via warp shuffle ----
        ull R0 = pack2(bd.x, 0.f), R1 = pack2(bd.y, 0.f);
        ull R2 = pack2(bd.z, 0.f), R3 = pack2(bd.w, 0.f);
        #pragma unroll
        for (int i = 0; i < L_DIM / 2; ++i) {
            const float ca = __shfl_sync(FULL, cor, 2 * i);
            const float cb = __shfl_sync(FULL, cor, 2 * i + 1);
            const ull cp = pack2(ca, cb);
            R0 = ffma2(wd2[0][i], cp, R0);
            R1 = ffma2(wd2[1][i], cp, R1);
            R2 = ffma2(wd2[2][i], cp, R2);
            R3 = ffma2(wd2[3][i], cp, R3);
        }
        float r0a, r0b, r1a, r1b, r2a, r2b, r3a, r3b;
        unpack2(R0, r0a, r0b); unpack2(R1, r1a, r1b);
        unpack2(R2, r2a, r2b); unpack2(R3, r3a, r3b);
        const float r0 = r0a + r0b, r1 = r1a + r1b;
        const float r2 = r2a + r2b, r3 = r3a + r3b;

        // ---- out_e2 partial (published now, consumed after NEXT barrier) ----
        float oss;
        {
            const ull o01 = pack2(r0, r1), o23 = pack2(r2, r3);
            ull op = mul2(o01, o01);
            op = ffma2(o23, o23, op);
            float olo, ohi; unpack2(op, olo, ohi);
            oss = olo + ohi;
        }
        #pragma unroll
        for (int off = 16; off > 0; off >>= 1)
            oss += __shfl_xor_sync(FULL, oss, off);
        if (lane == 0) sRed[p][wid * 32 + 25] = oss;

        // carry row state into next iteration's finalize
        pr0 = r0; pr1 = r1; pr2 = r2; pr3 = r3;
        pin_e2 = in_e2;
        prow_off = (size_t)row * D_DIM + c0;
        havePrev = true;

        dv = dnext;
        p ^= 1;
    }

    // ---- epilogue: finalize the last row ----
    __syncthreads();
    if (havePrev) {
        float oe2 = 0.0f;
        #pragma unroll
        for (int w = 0; w < TPB / 32; ++w)
            oe2 += sRed[1 - p][w * 32 + 25];
        const float s2 = pin_e2 / (sqrtf(oe2) + EPSV) * ep;
        float4 o;
        o.x = pr0 * s2; o.y = pr1 * s2; o.z = pr2 * s2; o.w = pr3 * s2;
        *reinterpret_cast<float4*>(&out[prow_off]) = o;
    }
}

extern "C" void kernel_launch(void* const* d_in, const int* in_sizes, int n_in,
                              void* d_out, int out_size)
{
    const float* data  = (const float*)d_in[0];
    const float* W_enc = (const float*)d_in[1];
    const float* b_enc = (const float*)d_in[2];
    const float* W_dec = (const float*)d_in[3];
    const float* b_dec = (const float*)d_in[4];
    const float* ecs   = (const float*)d_in[5];
    const float* ep    = (const float*)d_in[6];
    float* out = (float*)d_out;

    const int n_rows = in_sizes[0] / D_DIM;   // 32768

    int dev = 0;
    cudaGetDevice(&dev);
    int sms = 0;
    cudaDeviceGetAttribute(&sms, cudaDevAttrMultiProcessorCount, dev);
    if (sms <= 0) sms = 148;

    leech_fused_kernel<<<sms, TPB>>>(data, W_enc, b_enc, W_dec, b_dec,
                                     ecs, ep, out, n_rows);
}

// round 10
// speedup vs baseline: 1.0659x; 1.0659x over previous
#include <cuda_runtime.h>

#define D_DIM 1024
#define L_DIM 24
#define TPB   256
#define CPT   4           // columns per thread: 1024 / 256
#define EPSV  1e-8f
#define FULL  0xffffffffu

// dynamic shared: W_enc [24*1024] | sRed[2 parity][8 warps * 64 slots]
// per-warp slot map: row A -> proj 0..23, ss 24, oss 25 ; row B -> +32
#define SM_WE    0
#define SM_RED   (L_DIM * D_DIM)
#define SM_FLOATS (SM_RED + 2 * 8 * 64)
#define SM_BYTES  (SM_FLOATS * 4)

// value-split butterfly over one warp: reduces acc[24] (each lane holds partials
// for all 24 values) to per-value sums scattered across lanes by the static
// vid map; identical xor-pairwise tree to a naive 24x butterfly (bitwise equal).
#define SPLIT_BUTTERFLY(acc, fin)                                          \
    {                                                                      \
        float w12[12];                                                     \
        _Pragma("unroll")                                                  \
        for (int i = 0; i < 12; ++i) {                                     \
            float don = (lane & 16) ? acc[i] : acc[i + 12];                \
            float rec = __shfl_xor_sync(FULL, don, 16);                    \
            w12[i] = ((lane & 16) ? acc[i + 12] : acc[i]) + rec;           \
        }                                                                  \
        float w6[6];                                                       \
        _Pragma("unroll")                                                  \
        for (int i = 0; i < 6; ++i) {                                      \
            float don = (lane & 8) ? w12[i] : w12[i + 6];                  \
            float rec = __shfl_xor_sync(FULL, don, 8);                     \
            w6[i] = ((lane & 8) ? w12[i + 6] : w12[i]) + rec;              \
        }                                                                  \
        float w3[3];                                                       \
        _Pragma("unroll")                                                  \
        for (int i = 0; i < 3; ++i) {                                      \
            float don = (lane & 4) ? w6[i] : w6[i + 3];                    \
            float rec = __shfl_xor_sync(FULL, don, 4);                     \
            w3[i] = ((lane & 4) ? w6[i + 3] : w6[i]) + rec;                \
        }                                                                  \
        float don4 = (lane & 2) ? w3[0] : w3[2];                           \
        float rec4 = __shfl_xor_sync(FULL, don4, 2);                       \
        float n0 = ((lane & 2) ? w3[2] : w3[0]) + rec4;                    \
        float n1 = w3[1] + __shfl_xor_sync(FULL, w3[1], 2);                \
        float don5 = (lane & 1) ? n0 : n1;                                 \
        float rec5 = __shfl_xor_sync(FULL, don5, 1);                       \
        fin = ((lane & 1) ? n1 : n0) + rec5;                               \
    }

__global__ __launch_bounds__(TPB, 1)
void leech_fused_kernel(const float* __restrict__ data,
                        const float* __restrict__ W_enc,
                        const float* __restrict__ b_enc,
                        const float* __restrict__ W_dec,
                        const float* __restrict__ b_dec,
                        const float* __restrict__ ecs_p,
                        const float* __restrict__ ep_p,
                        float* __restrict__ out,
                        int n_rows)
{
    extern __shared__ float smem[];
    float* sWe  = smem + SM_WE;
    float* sRed = smem + SM_RED;

    const int t    = threadIdx.x;
    const int wid  = t >> 5;
    const int lane = t & 31;
    const int c0   = t * CPT;

    // ---- prologue: W_enc -> shared (natural [L][D] layout), W_dec -> regs ----
    {
        const float4* src = reinterpret_cast<const float4*>(W_enc);
        float4* dst = reinterpret_cast<float4*>(sWe);
        #pragma unroll
        for (int i = 0; i < (L_DIM * D_DIM / 4) / TPB; ++i)
            dst[i * TPB + t] = src[i * TPB + t];
    }
    float wd[CPT][L_DIM];                // W_dec[c0+j][l] — 96 regs
    #pragma unroll
    for (int j = 0; j < CPT; ++j) {
        #pragma unroll
        for (int l = 0; l < L_DIM; l += 4) {
            float4 v = *reinterpret_cast<const float4*>(&W_dec[(c0 + j) * L_DIM + l]);
            wd[j][l + 0] = v.x; wd[j][l + 1] = v.y;
            wd[j][l + 2] = v.z; wd[j][l + 3] = v.w;
        }
    }
    const float4 bd  = *reinterpret_cast<const float4*>(&b_dec[c0]);
    const float  ecs = ecs_p[0];
    const float  ep  = ep_p[0];
    const float  benc = (lane < L_DIM) ? b_enc[lane] : 0.0f;

    // split-butterfly final lane -> value-id map (lanes with (lane&3)==3 hold dups)
    const bool dup = ((lane & 3) == 3);
    const int  vid = 12 * ((lane >> 4) & 1) + 6 * ((lane >> 3) & 1)
                   + 3 * ((lane >> 2) & 1) + ((lane & 2) ? 2 : (lane & 1));

    __syncthreads();

    const int stride  = gridDim.x;
    const int stride2 = 2 * stride;
    int rowA = blockIdx.x;

    float4 dA = make_float4(0.f, 0.f, 0.f, 0.f);
    float4 dB = make_float4(0.f, 0.f, 0.f, 0.f);
    if (rowA < n_rows)
        dA = *reinterpret_cast<const float4*>(&data[(size_t)rowA * D_DIM + c0]);
    if (rowA + stride < n_rows)
        dB = *reinterpret_cast<const float4*>(&data[(size_t)(rowA + stride) * D_DIM + c0]);

    int p = 0;   // sRed parity

    for (; rowA < n_rows; rowA += stride2) {
        const int rowB = rowA + stride;
        float* red = sRed + p * (8 * 64);

        // ---- encode both rows: W_enc float4 loaded once, used twice ----
        float accA[L_DIM], accB[L_DIM];
        #pragma unroll
        for (int l = 0; l < L_DIM; ++l) {
            float4 w = *reinterpret_cast<const float4*>(&sWe[l * D_DIM + c0]);
            float a = dA.x * w.x;
            a = fmaf(dA.y, w.y, a);
            a = fmaf(dA.z, w.z, a);
            a = fmaf(dA.w, w.w, a);
            accA[l] = a;
            float b = dB.x * w.x;
            b = fmaf(dB.y, w.y, b);
            b = fmaf(dB.z, w.z, b);
            b = fmaf(dB.w, w.w, b);
            accB[l] = b;
        }
        float ssA = dA.x * dA.x + dA.y * dA.y + dA.z * dA.z + dA.w * dA.w;
        float ssB = dB.x * dB.x + dB.y * dB.y + dB.z * dB.z + dB.w * dB.w;

        // ---- prefetch next pair (dA/dB dead after encode) ----
        const int nA = rowA + stride2;
        const int nB = nA + stride;
        float4 dAn = make_float4(0.f, 0.f, 0.f, 0.f);
        float4 dBn = make_float4(0.f, 0.f, 0.f, 0.f);
        if (nA < n_rows)
            dAn = *reinterpret_cast<const float4*>(&data[(size_t)nA * D_DIM + c0]);
        if (nB < n_rows)
            dBn = *reinterpret_cast<const float4*>(&data[(size_t)nB * D_DIM + c0]);

        // ---- two independent split butterflies (chains interleave in scheduler) ----
        float finA, finB;
        SPLIT_BUTTERFLY(accA, finA)
        SPLIT_BUTTERFLY(accB, finB)

        #pragma unroll
        for (int off = 16; off > 0; off >>= 1) {
            ssA += __shfl_xor_sync(FULL, ssA, off);
            ssB += __shfl_xor_sync(FULL, ssB, off);
        }

        if (!dup) {
            red[wid * 64 + vid]      = finA;
            red[wid * 64 + 32 + vid] = finB;
        }
        if (lane == 3) {
            red[wid * 64 + 24] = ssA;
            red[wid * 64 + 56] = ssB;
        }
        __syncthreads();                               // barrier 1 (per pair)

        // ---- lattice math, both rows, redundantly per warp (bitwise identical) ----
        float sA = 0.0f, sB = 0.0f;
        if (lane <= L_DIM) {
            #pragma unroll
            for (int w = 0; w < TPB / 32; ++w) {
                sA += red[w * 64 + lane];
                sB += red[w * 64 + 32 + lane];
            }
        }
        const float in_eA = sqrtf(__shfl_sync(FULL, sA, L_DIM));
        const float in_eB = sqrtf(__shfl_sync(FULL, sB, L_DIM));

        float lpA = 0.0f, lpB = 0.0f;
        if (lane < L_DIM) {
            lpA = rintf((sA + benc) / ecs) * ecs;      // exact div + half-even round
            lpB = rintf((sB + benc) / ecs) * ecs;
        }
        float qA = lpA * lpA, qB = lpB * lpB;
        #pragma unroll
        for (int off = 16; off > 0; off >>= 1) {
            qA += __shfl_xor_sync(FULL, qA, off);
            qB += __shfl_xor_sync(FULL, qB, off);
        }
        const float out_eA = sqrtf(qA);
        const float out_eB = sqrtf(qB);

        const float s1A = in_eA / (out_eA + EPSV) * ep;
        const float s1B = in_eB / (out_eB + EPSV) * ep;
        const float latA = lpA * s1A, latB = lpB * s1B;
        const float corA = (fabsf(latA) > ecs) ? latA : 0.0f;
        const float corB = (fabsf(latB) > ecs) ? latB : 0.0f;
        const float in_e2A = fabsf(s1A) * out_eA;      // ||lattice_A||
        const float in_e2B = fabsf(s1B) * out_eB;

        // ---- decode both rows: W_dec regs shared across rows, cor via shfl ----
        float rA0 = bd.x, rA1 = bd.y, rA2 = bd.z, rA3 = bd.w;
        float rB0 = bd.x, rB1 = bd.y, rB2 = bd.z, rB3 = bd.w;
        #pragma unroll
        for (int l = 0; l < L_DIM; ++l) {
            const float cA = __shfl_sync(FULL, corA, l);
            const float cB = __shfl_sync(FULL, corB, l);
            rA0 = fmaf(cA, wd[0][l], rA0);
            rA1 = fmaf(cA, wd[1][l], rA1);
            rA2 = fmaf(cA, wd[2][l], rA2);
            rA3 = fmaf(cA, wd[3][l], rA3);
            rB0 = fmaf(cB, wd[0][l], rB0);
            rB1 = fmaf(cB, wd[1][l], rB1);
            rB2 = fmaf(cB, wd[2][l], rB2);
            rB3 = fmaf(cB, wd[3][l], rB3);
        }

        // ---- out_e2 reductions ----
        float ossA = rA0 * rA0 + rA1 * rA1 + rA2 * rA2 + rA3 * rA3;
        float ossB = rB0 * rB0 + rB1 * rB1 + rB2 * rB2 + rB3 * rB3;
        #pragma unroll
        for (int off = 16; off > 0; off >>= 1) {
            ossA += __shfl_xor_sync(FULL, ossA, off);
            ossB += __shfl_xor_sync(FULL, ossB, off);
        }
        if (lane == 0) {
            red[wid * 64 + 25] = ossA;
            red[wid * 64 + 57] = ossB;
        }
        __syncthreads();                               // barrier 2 (per pair)

        float oe2A = 0.0f, oe2B = 0.0f;
        #pragma unroll
        for (int w = 0; w < TPB / 32; ++w) {
            oe2A += red[w * 64 + 25];
            oe2B += red[w * 64 + 57];
        }

        const float s2A = in_e2A / (sqrtf(oe2A) + EPSV) * ep;
        const float s2B = in_e2B / (sqrtf(oe2B) + EPSV) * ep;

        float4 oA, oB;
        oA.x = rA0 * s2A; oA.y = rA1 * s2A; oA.z = rA2 * s2A; oA.w = rA3 * s2A;
        oB.x = rB0 * s2B; oB.y = rB1 * s2B; oB.z = rB2 * s2B; oB.w = rB3 * s2B;
        *reinterpret_cast<float4*>(&out[(size_t)rowA * D_DIM + c0]) = oA;
        if (rowB < n_rows)
            *reinterpret_cast<float4*>(&out[(size_t)rowB * D_DIM + c0]) = oB;

        dA = dAn;
        dB = dBn;
        p ^= 1;     // parity flip removes the finalize-read vs next-publish WAR hazard
    }
}

extern "C" void kernel_launch(void* const* d_in, const int* in_sizes, int n_in,
                              void* d_out, int out_size)
{
    const float* data  = (const float*)d_in[0];
    const float* W_enc = (const float*)d_in[1];
    const float* b_enc = (const float*)d_in[2];
    const float* W_dec = (const float*)d_in[3];
    const float* b_dec = (const float*)d_in[4];
    const float* ecs   = (const float*)d_in[5];
    const float* ep    = (const float*)d_in[6];
    float* out = (float*)d_out;

    const int n_rows = in_sizes[0] / D_DIM;   // 32768

    int dev = 0;
    cudaGetDevice(&dev);
    int sms = 0;
    cudaDeviceGetAttribute(&sms, cudaDevAttrMultiProcessorCount, dev);
    if (sms <= 0) sms = 148;

    cudaFuncSetAttribute(leech_fused_kernel,
                         cudaFuncAttributeMaxDynamicSharedMemorySize, SM_BYTES);

    leech_fused_kernel<<<sms, TPB, SM_BYTES>>>(data, W_enc, b_enc, W_dec, b_dec,
                                               ecs, ep, out, n_rows);
}

// round 12
// speedup vs baseline: 1.1922x; 1.1185x over previous
#include <cuda_runtime.h>

#define D_DIM 1024
#define L_DIM 24
#define TPB   256
#define CPT   4           // columns per thread: 1024 / 256
#define EPSV  1e-8f
#define FULL  0xffffffffu

// dynamic shared (floats):
//   W_enc [24*1024] | sRed[2 parity][8 warps * 96 slots] | sCor[96]
// per-warp red slots: rowA proj 0..23 ss 24 oss 25 ; rowB +32 ; rowC +64
#define SM_WE     0
#define SM_RED    (L_DIM * D_DIM)
#define SM_COR    (SM_RED + 2 * 8 * 96)
#define SM_FLOATS (SM_COR + 96)
#define SM_BYTES  (SM_FLOATS * 4)

// value-split butterfly: reduces acc[24] (each lane holds partials for all 24
// values) to per-value sums scattered across lanes by the static vid map;
// identical xor-pairwise tree to a naive 24x butterfly (bitwise equal).
#define SPLIT_BUTTERFLY(acc, fin)                                          \
    {                                                                      \
        float w12[12];                                                     \
        _Pragma("unroll")                                                  \
        for (int i = 0; i < 12; ++i) {                                     \
            float don = (lane & 16) ? acc[i] : acc[i + 12];                \
            float rec = __shfl_xor_sync(FULL, don, 16);                    \
            w12[i] = ((lane & 16) ? acc[i + 12] : acc[i]) + rec;           \
        }                                                                  \
        float w6[6];                                                       \
        _Pragma("unroll")                                                  \
        for (int i = 0; i < 6; ++i) {                                      \
            float don = (lane & 8) ? w12[i] : w12[i + 6];                  \
            float rec = __shfl_xor_sync(FULL, don, 8);                     \
            w6[i] = ((lane & 8) ? w12[i + 6] : w12[i]) + rec;              \
        }                                                                  \
        float w3[3];                                                       \
        _Pragma("unroll")                                                  \
        for (int i = 0; i < 3; ++i) {                                      \
            float don = (lane & 4) ? w6[i] : w6[i + 3];                    \
            float rec = __shfl_xor_sync(FULL, don, 4);                     \
            w3[i] = ((lane & 4) ? w6[i + 3] : w6[i]) + rec;                \
        }                                                                  \
        float don4 = (lane & 2) ? w3[0] : w3[2];                           \
        float rec4 = __shfl_xor_sync(FULL, don4, 2);                       \
        float n0 = ((lane & 2) ? w3[2] : w3[0]) + rec4;                    \
        float n1 = w3[1] + __shfl_xor_sync(FULL, w3[1], 2);                \
        float don5 = (lane & 1) ? n0 : n1;                                 \
        float rec5 = __shfl_xor_sync(FULL, don5, 1);                       \
        fin = ((lane & 1) ? n1 : n0) + rec5;                               \
    }

__global__ __launch_bounds__(TPB, 1)
void leech_fused_kernel(const float* __restrict__ data,
                        const float* __restrict__ W_enc,
                        const float* __restrict__ b_enc,
                        const float* __restrict__ W_dec,
                        const float* __restrict__ b_dec,
                        const float* __restrict__ ecs_p,
                        const float* __restrict__ ep_p,
                        float* __restrict__ out,
                        int n_rows)
{
    extern __shared__ float smem[];
    float* sWe   = smem + SM_WE;
    float* sRed  = smem + SM_RED;
    float* sCorA = smem + SM_COR;
    float* sCorB = smem + SM_COR + 32;
    float* sCorC = smem + SM_COR + 64;

    const int t    = threadIdx.x;
    const int wid  = t >> 5;
    const int lane = t & 31;
    const int c0   = t * CPT;

    // ---- prologue: W_enc -> shared, W_dec -> regs ----
    {
        const float4* src = reinterpret_cast<const float4*>(W_enc);
        float4* dst = reinterpret_cast<float4*>(sWe);
        #pragma unroll
        for (int i = 0; i < (L_DIM * D_DIM / 4) / TPB; ++i)
            dst[i * TPB + t] = src[i * TPB + t];
    }
    float wd[CPT][L_DIM];                // W_dec[c0+j][l] — 96 regs
    #pragma unroll
    for (int j = 0; j < CPT; ++j) {
        #pragma unroll
        for (int l = 0; l < L_DIM; l += 4) {
            float4 v = *reinterpret_cast<const float4*>(&W_dec[(c0 + j) * L_DIM + l]);
            wd[j][l + 0] = v.x; wd[j][l + 1] = v.y;
            wd[j][l + 2] = v.z; wd[j][l + 3] = v.w;
        }
    }
    const float4 bd  = *reinterpret_cast<const float4*>(&b_dec[c0]);
    const float  ecs = ecs_p[0];
    const float  ep  = ep_p[0];
    const float  benc = (lane < L_DIM) ? b_enc[lane] : 0.0f;

    // split-butterfly final lane -> value-id map (lanes with (lane&3)==3 hold dups)
    const bool dup = ((lane & 3) == 3);
    const int  vid = 12 * ((lane >> 4) & 1) + 6 * ((lane >> 3) & 1)
                   + 3 * ((lane >> 2) & 1) + ((lane & 2) ? 2 : (lane & 1));

    __syncthreads();

    const int stride  = gridDim.x;
    const int stride3 = 3 * stride;
    int rowA = blockIdx.x;

    float4 dA = make_float4(0.f, 0.f, 0.f, 0.f);
    float4 dB = make_float4(0.f, 0.f, 0.f, 0.f);
    float4 dC = make_float4(0.f, 0.f, 0.f, 0.f);
    if (rowA < n_rows)
        dA = *reinterpret_cast<const float4*>(&data[(size_t)rowA * D_DIM + c0]);
    if (rowA + stride < n_rows)
        dB = *reinterpret_cast<const float4*>(&data[(size_t)(rowA + stride) * D_DIM + c0]);
    if (rowA + 2 * stride < n_rows)
        dC = *reinterpret_cast<const float4*>(&data[(size_t)(rowA + 2 * stride) * D_DIM + c0]);

    int p = 0;   // sRed parity

    for (; rowA < n_rows; rowA += stride3) {
        const int rowB = rowA + stride;
        const int rowC = rowB + stride;
        float* red = sRed + p * (8 * 96);

        // ---- encode 3 rows: each W_enc float4 loaded once, used 3x ----
        float accA[L_DIM], accB[L_DIM], accC[L_DIM];
        #pragma unroll
        for (int l = 0; l < L_DIM; ++l) {
            float4 w = *reinterpret_cast<const float4*>(&sWe[l * D_DIM + c0]);
            float a = dA.x * w.x;
            a = fmaf(dA.y, w.y, a); a = fmaf(dA.z, w.z, a); a = fmaf(dA.w, w.w, a);
            accA[l] = a;
            float b = dB.x * w.x;
            b = fmaf(dB.y, w.y, b); b = fmaf(dB.z, w.z, b); b = fmaf(dB.w, w.w, b);
            accB[l] = b;
            float c = dC.x * w.x;
            c = fmaf(dC.y, w.y, c); c = fmaf(dC.z, w.z, c); c = fmaf(dC.w, w.w, c);
            accC[l] = c;
        }
        float ssA = dA.x * dA.x + dA.y * dA.y + dA.z * dA.z + dA.w * dA.w;
        float ssB = dB.x * dB.x + dB.y * dB.y + dB.z * dB.z + dB.w * dB.w;
        float ssC = dC.x * dC.x + dC.y * dC.y + dC.z * dC.z + dC.w * dC.w;

        // ---- prefetch next triple (dA/dB/dC dead after encode) ----
        const int nA = rowA + stride3, nB = nA + stride, nC = nB + stride;
        float4 dAn = make_float4(0.f, 0.f, 0.f, 0.f);
        float4 dBn = make_float4(0.f, 0.f, 0.f, 0.f);
        float4 dCn = make_float4(0.f, 0.f, 0.f, 0.f);
        if (nA < n_rows)
            dAn = *reinterpret_cast<const float4*>(&data[(size_t)nA * D_DIM + c0]);
        if (nB < n_rows)
            dBn = *reinterpret_cast<const float4*>(&data[(size_t)nB * D_DIM + c0]);
        if (nC < n_rows)
            dCn = *reinterpret_cast<const float4*>(&data[(size_t)nC * D_DIM + c0]);

        // ---- three independent split butterflies ----
        float finA, finB, finC;
        SPLIT_BUTTERFLY(accA, finA)
        SPLIT_BUTTERFLY(accB, finB)
        SPLIT_BUTTERFLY(accC, finC)

        #pragma unroll
        for (int off = 16; off > 0; off >>= 1) {
            ssA += __shfl_xor_sync(FULL, ssA, off);
            ssB += __shfl_xor_sync(FULL, ssB, off);
            ssC += __shfl_xor_sync(FULL, ssC, off);
        }

        if (!dup) {
            red[wid * 96 + vid]      = finA;
            red[wid * 96 + 32 + vid] = finB;
            red[wid * 96 + 64 + vid] = finC;
        }
        if (lane == 3) {
            red[wid * 96 + 24] = ssA;
            red[wid * 96 + 56] = ssB;
            red[wid * 96 + 88] = ssC;
        }
        __syncthreads();                               // barrier 1 (per triple)

        // ---- lattice math, 3 rows, redundant per warp (bitwise identical) ----
        float sA = 0.0f, sB = 0.0f, sC = 0.0f;
        if (lane <= L_DIM) {
            #pragma unroll
            for (int w = 0; w < TPB / 32; ++w) {
                sA += red[w * 96 + lane];
                sB += red[w * 96 + 32 + lane];
                sC += red[w * 96 + 64 + lane];
            }
        }
        const float in_eA = sqrtf(__shfl_sync(FULL, sA, L_DIM));
        const float in_eB = sqrtf(__shfl_sync(FULL, sB, L_DIM));
        const float in_eC = sqrtf(__shfl_sync(FULL, sC, L_DIM));

        float lpA = 0.0f, lpB = 0.0f, lpC = 0.0f;
        if (lane < L_DIM) {
            lpA = rintf((sA + benc) / ecs) * ecs;      // exact div + half-even round
            lpB = rintf((sB + benc) / ecs) * ecs;
            lpC = rintf((sC + benc) / ecs) * ecs;
        }
        float qA = lpA * lpA, qB = lpB * lpB, qC = lpC * lpC;
        #pragma unroll
        for (int off = 16; off > 0; off >>= 1) {
            qA += __shfl_xor_sync(FULL, qA, off);
            qB += __shfl_xor_sync(FULL, qB, off);
            qC += __shfl_xor_sync(FULL, qC, off);
        }
        const float out_eA = sqrtf(qA), out_eB = sqrtf(qB), out_eC = sqrtf(qC);

        const float s1A = in_eA / (out_eA + EPSV) * ep;
        const float s1B = in_eB / (out_eB + EPSV) * ep;
        const float s1C = in_eC / (out_eC + EPSV) * ep;
        const float latA = lpA * s1A, latB = lpB * s1B, latC = lpC * s1C;
        const float corA = (fabsf(latA) > ecs) ? latA : 0.0f;
        const float corB = (fabsf(latB) > ecs) ? latB : 0.0f;
        const float corC = (fabsf(latC) > ecs) ? latC : 0.0f;
        const float in_e2A = fabsf(s1A) * out_eA;      // ||lattice||
        const float in_e2B = fabsf(s1B) * out_eB;
        const float in_e2C = fabsf(s1C) * out_eC;

        // ---- publish cor to shared (all warps write IDENTICAL values: benign
        //      race; each warp reads only after its own write -> no barrier) ----
        if (lane < L_DIM) {
            sCorA[lane] = corA;
            sCorB[lane] = corB;
            sCorC[lane] = corC;
        }
        __syncwarp();

        // ---- decode 3 rows: W_dec regs shared, cor via LDS.128 broadcast ----
        float rA0 = bd.x, rA1 = bd.y, rA2 = bd.z, rA3 = bd.w;
        float rB0 = bd.x, rB1 = bd.y, rB2 = bd.z, rB3 = bd.w;
        float rC0 = bd.x, rC1 = bd.y, rC2 = bd.z, rC3 = bd.w;
        #pragma unroll
        for (int l = 0; l < L_DIM; l += 4) {
            const float4 cA4 = *reinterpret_cast<const float4*>(&sCorA[l]);
            const float4 cB4 = *reinterpret_cast<const float4*>(&sCorB[l]);
            const float4 cC4 = *reinterpret_cast<const float4*>(&sCorC[l]);
            const float cAv[4] = {cA4.x, cA4.y, cA4.z, cA4.w};
            const float cBv[4] = {cB4.x, cB4.y, cB4.z, cB4.w};
            const float cCv[4] = {cC4.x, cC4.y, cC4.z, cC4.w};
            #pragma unroll
            for (int k = 0; k < 4; ++k) {
                rA0 = fmaf(cAv[k], wd[0][l + k], rA0);
                rA1 = fmaf(cAv[k], wd[1][l + k], rA1);
                rA2 = fmaf(cAv[k], wd[2][l + k], rA2);
                rA3 = fmaf(cAv[k], wd[3][l + k], rA3);
                rB0 = fmaf(cBv[k], wd[0][l + k], rB0);
                rB1 = fmaf(cBv[k], wd[1][l + k], rB1);
                rB2 = fmaf(cBv[k], wd[2][l + k], rB2);
                rB3 = fmaf(cBv[k], wd[3][l + k], rB3);
                rC0 = fmaf(cCv[k], wd[0][l + k], rC0);
                rC1 = fmaf(cCv[k], wd[1][l + k], rC1);
                rC2 = fmaf(cCv[k], wd[2][l + k], rC2);
                rC3 = fmaf(cCv[k], wd[3][l + k], rC3);
            }
        }

        // ---- out_e2 reductions ----
        float ossA = rA0 * rA0 + rA1 * rA1 + rA2 * rA2 + rA3 * rA3;
        float ossB = rB0 * rB0 + rB1 * rB1 + rB2 * rB2 + rB3 * rB3;
        float ossC = rC0 * rC0 + rC1 * rC1 + rC2 * rC2 + rC3 * rC3;
        #pragma unroll
        for (int off = 16; off > 0; off >>= 1) {
            ossA += __shfl_xor_sync(FULL, ossA, off);
            ossB += __shfl_xor_sync(FULL, ossB, off);
            ossC += __shfl_xor_sync(FULL, ossC, off);
        }
        if (lane == 0) {
            red[wid * 96 + 25] = ossA;
            red[wid * 96 + 57] = ossB;
            red[wid * 96 + 89] = ossC;
        }
        __syncthreads();                               // barrier 2 (per triple)

        float oe2A = 0.0f, oe2B = 0.0f, oe2C = 0.0f;
        #pragma unroll
        for (int w = 0; w < TPB / 32; ++w) {
            oe2A += red[w * 96 + 25];
            oe2B += red[w * 96 + 57];
            oe2C += red[w * 96 + 89];
        }

        const float s2A = in_e2A / (sqrtf(oe2A) + EPSV) * ep;
        const float s2B = in_e2B / (sqrtf(oe2B) + EPSV) * ep;
        const float s2C = in_e2C / (sqrtf(oe2C) + EPSV) * ep;

        float4 oA, oB, oC;
        oA.x = rA0 * s2A; oA.y = rA1 * s2A; oA.z = rA2 * s2A; oA.w = rA3 * s2A;
        oB.x = rB0 * s2B; oB.y = rB1 * s2B; oB.z = rB2 * s2B; oB.w = rB3 * s2B;
        oC.x = rC0 * s2C; oC.y = rC1 * s2C; oC.z = rC2 * s2C; oC.w = rC3 * s2C;
        *reinterpret_cast<float4*>(&out[(size_t)rowA * D_DIM + c0]) = oA;
        if (rowB < n_rows)
            *reinterpret_cast<float4*>(&out[(size_t)rowB * D_DIM + c0]) = oB;
        if (rowC < n_rows)
            *reinterpret_cast<float4*>(&out[(size_t)rowC * D_DIM + c0]) = oC;

        dA = dAn; dB = dBn; dC = dCn;
        p ^= 1;     // parity flip kills proj/oss WAR hazards across iterations
    }
}

extern "C" void kernel_launch(void* const* d_in, const int* in_sizes, int n_in,
                              void* d_out, int out_size)
{
    const float* data  = (const float*)d_in[0];
    const float* W_enc = (const float*)d_in[1];
    const float* b_enc = (const float*)d_in[2];
    const float* W_dec = (const float*)d_in[3];
    const float* b_dec = (const float*)d_in[4];
    const float* ecs   = (const float*)d_in[5];
    const float* ep    = (const float*)d_in[6];
    float* out = (float*)d_out;

    const int n_rows = in_sizes[0] / D_DIM;   // 32768

    int dev = 0;
    cudaGetDevice(&dev);
    int sms = 0;
    cudaDeviceGetAttribute(&sms, cudaDevAttrMultiProcessorCount, dev);
    if (sms <= 0) sms = 148;

    cudaFuncSetAttribute(leech_fused_kernel,
                         cudaFuncAttributeMaxDynamicSharedMemorySize, SM_BYTES);

    leech_fused_kernel<<<sms, TPB, SM_BYTES>>>(data, W_enc, b_enc, W_dec, b_dec,
                                               ecs, ep, out, n_rows);
}